// round 5
// baseline (speedup 1.0000x reference)
#include <cuda_runtime.h>

#define M_TOTAL 16384   // 16 * 1024 queries
#define N_CODES 8192
#define DIMC    256
#define QUANT_ELEMS (M_TOTAL * DIMC)

// ---- scratch (no device allocation allowed) ----
__device__ float g_esq[N_CODES];
__device__ float g_qsq[M_TOTAL];
__device__ int   g_idx[M_TOTAL];
__device__ float g_loss;

// ---- Blackwell packed fp32 helpers ----
// fma.rn.f32x2: two INDEPENDENT round-to-nearest fp32 FMAs per instruction.
// Lane0 = low 32 bits, lane1 = high 32 bits. Accumulation order per lane is
// identical to scalar fmaf chains -> bitwise identical results.
__device__ __forceinline__ void ffma2(unsigned long long& acc,
                                      unsigned long long a2,
                                      unsigned long long b2) {
    asm("fma.rn.f32x2 %0, %1, %2, %0;" : "+l"(acc) : "l"(a2), "l"(b2));
}
__device__ __forceinline__ unsigned long long dup2(float x) {
    unsigned long long r;
    asm("mov.b64 %0, {%1, %1};" : "=l"(r) : "r"(__float_as_uint(x)));
    return r;
}
__device__ __forceinline__ float lo2(unsigned long long v) {
    return __uint_as_float((unsigned int)(v & 0xffffffffu));
}
__device__ __forceinline__ float hi2(unsigned long long v) {
    return __uint_as_float((unsigned int)(v >> 32));
}

// ============================================================
// Kernel A: row squared-norms (one warp per 256-float row).
// which==0 -> g_esq (embedding), also zeroes g_loss. which==1 -> g_qsq.
// ============================================================
__global__ void rowsq_kernel(const float* __restrict__ src, int nrows, int which) {
    if (which == 0 && blockIdx.x == 0 && threadIdx.x == 0) g_loss = 0.0f;
    float* dst = which ? g_qsq : g_esq;
    int warp = (blockIdx.x * blockDim.x + threadIdx.x) >> 5;
    int lane = threadIdx.x & 31;
    if (warp >= nrows) return;
    const float4* row = (const float4*)(src + (size_t)warp * DIMC);
    float s = 0.0f;
    #pragma unroll
    for (int i = 0; i < 2; i++) {
        float4 v = row[lane + 32 * i];
        s += v.x * v.x + v.y * v.y + v.z * v.z + v.w * v.w;
    }
    #pragma unroll
    for (int o = 16; o > 0; o >>= 1) s += __shfl_xor_sync(0xFFFFFFFFu, s, o);
    if (lane == 0) dst[warp] = s;
}

// ============================================================
// Kernel B: fused distance-GEMM + argmin, FFMA2 (f32x2) mainloop.
// CTA tile: 128 queries x 128 codes, K chunked by 32 through smem.
// 256 threads; each owns an 8(i) x 8(j) register tile stored as
// 4 i-pairs x 8 j columns of packed f32x2 accumulators.
//
// Distance replicates the reference's fp32 rounding:
//   A = fl(q_sq + e_sq); d = fl(A - 2*dot) via fmaf(-2, dot, A).
// Ties break to the LOWEST index (strict <, ascending n).
// ============================================================
#define MT 128
#define NT 128
#define KC 32

__global__ __launch_bounds__(256, 2)
void argmin_kernel(const float* __restrict__ Q, const float* __restrict__ E) {
    __shared__ float qs[KC][MT];   // 16 KB
    __shared__ float es[KC][NT];   // 16 KB

    const int tid = threadIdx.x;
    const int tx = tid & 15;       // code-column group (8 cols)
    const int ty = tid >> 4;       // query-row group (8 rows)
    const int m0 = blockIdx.x * MT;

    float qsq_r[8];
    #pragma unroll
    for (int i = 0; i < 8; i++) qsq_r[i] = g_qsq[m0 + ty * 8 + i];

    float minv[8];
    int   mini[8];
    #pragma unroll
    for (int i = 0; i < 8; i++) { minv[i] = 3.4e38f; mini[i] = 0; }

    for (int n0 = 0; n0 < N_CODES; n0 += NT) {
        // acc2[i2][j]: lane-lo = query row 2*i2, lane-hi = row 2*i2+1
        unsigned long long acc2[4][8];
        #pragma unroll
        for (int i2 = 0; i2 < 4; i2++)
            #pragma unroll
            for (int j = 0; j < 8; j++) acc2[i2][j] = 0ull;

        for (int k0 = 0; k0 < DIMC; k0 += KC) {
            // cooperative load: 128 rows x 32 cols each for Q-tile and E-tile
            #pragma unroll
            for (int it = 0; it < 4; it++) {
                int f4 = tid + 256 * it;   // 0..1023
                int r  = f4 >> 3;          // row 0..127
                int c4 = f4 & 7;           // float4 column 0..7
                float4 v = *(const float4*)(Q + (size_t)(m0 + r) * DIMC + k0 + c4 * 4);
                qs[c4 * 4 + 0][r] = v.x; qs[c4 * 4 + 1][r] = v.y;
                qs[c4 * 4 + 2][r] = v.z; qs[c4 * 4 + 3][r] = v.w;
                float4 w = *(const float4*)(E + (size_t)(n0 + r) * DIMC + k0 + c4 * 4);
                es[c4 * 4 + 0][r] = w.x; es[c4 * 4 + 1][r] = w.y;
                es[c4 * 4 + 2][r] = w.z; es[c4 * 4 + 3][r] = w.w;
            }
            __syncthreads();

            #pragma unroll 8
            for (int kk = 0; kk < KC; kk++) {
                // a: 4 naturally-packed (i,i+1) pairs straight from smem
                ulonglong2 a01 = *(const ulonglong2*)&qs[kk][ty * 8];
                ulonglong2 a23 = *(const ulonglong2*)&qs[kk][ty * 8 + 4];
                unsigned long long a2[4] = {a01.x, a01.y, a23.x, a23.y};
                // b: 8 duplicated columns
                float4 b0 = *(const float4*)&es[kk][tx * 8];
                float4 b1 = *(const float4*)&es[kk][tx * 8 + 4];
                unsigned long long bd[8];
                bd[0] = dup2(b0.x); bd[1] = dup2(b0.y);
                bd[2] = dup2(b0.z); bd[3] = dup2(b0.w);
                bd[4] = dup2(b1.x); bd[5] = dup2(b1.y);
                bd[6] = dup2(b1.z); bd[7] = dup2(b1.w);
                #pragma unroll
                for (int i2 = 0; i2 < 4; i2++)
                    #pragma unroll
                    for (int j = 0; j < 8; j++)
                        ffma2(acc2[i2][j], a2[i2], bd[j]);
            }
            __syncthreads();
        }

        // argmin update, ascending n within each thread (strict < keeps
        // the lowest tied index, matching jnp.argmin)
        #pragma unroll
        for (int j = 0; j < 8; j++) {
            int n = n0 + tx * 8 + j;
            float eq = __ldg(&g_esq[n]);
            #pragma unroll
            for (int i2 = 0; i2 < 4; i2++) {
                float dot_lo = lo2(acc2[i2][j]);
                float dot_hi = hi2(acc2[i2][j]);
                {
                    int i = 2 * i2;
                    float A = __fadd_rn(qsq_r[i], eq);
                    float d = fmaf(-2.0f, dot_lo, A);
                    if (d < minv[i]) { minv[i] = d; mini[i] = n; }
                }
                {
                    int i = 2 * i2 + 1;
                    float A = __fadd_rn(qsq_r[i], eq);
                    float d = fmaf(-2.0f, dot_hi, A);
                    if (d < minv[i]) { minv[i] = d; mini[i] = n; }
                }
            }
        }
    }

    // cross-thread reduction: 16 candidates per query row. Reuse qs/es smem.
    float* rv = &qs[0][0];
    int*   ri = (int*)&es[0][0];
    #pragma unroll
    for (int i = 0; i < 8; i++) {
        rv[(ty * 8 + i) * 16 + tx] = minv[i];
        ri[(ty * 8 + i) * 16 + tx] = mini[i];
    }
    __syncthreads();
    if (tid < MT) {
        float best = rv[tid * 16];
        int   bi   = ri[tid * 16];
        #pragma unroll
        for (int t = 1; t < 16; t++) {
            float v = rv[tid * 16 + t];
            int  id = ri[tid * 16 + t];
            if (v < best || (v == best && id < bi)) { best = v; bi = id; }
        }
        g_idx[m0 + tid] = bi;
    }
}

// ============================================================
// Kernel C: gather quantized vectors, write indices + ST output,
// accumulate sum of (q - e)^2 for the loss. One block per query.
// ============================================================
__global__ void gather_kernel(const float* __restrict__ Q,
                              const float* __restrict__ E,
                              float* __restrict__ out) {
    const int m = blockIdx.x;
    const int c = threadIdx.x;           // 256 threads = DIMC
    const int idx = g_idx[m];
    float q = Q[(size_t)m * DIMC + c];
    float e = E[(size_t)idx * DIMC + c];
    // straight-through, computed as the reference does: q + (e - q)
    out[M_TOTAL + (size_t)m * DIMC + c] = __fadd_rn(q, __fsub_rn(e, q));
    float d = q - e;
    float s = d * d;
    #pragma unroll
    for (int o = 16; o > 0; o >>= 1) s += __shfl_xor_sync(0xFFFFFFFFu, s, o);
    __shared__ float ws[8];
    int lane = c & 31, warp = c >> 5;
    if (lane == 0) ws[warp] = s;
    __syncthreads();
    if (c == 0) {
        float t = 0.0f;
        #pragma unroll
        for (int w = 0; w < 8; w++) t += ws[w];
        atomicAdd(&g_loss, t);
        out[m] = (float)idx;             // index output as float
    }
}

// ============================================================
// Kernel D: finalize vq_loss = 1.25 * mean((q - e)^2)
// ============================================================
__global__ void final_kernel(float* __restrict__ out) {
    out[M_TOTAL + (size_t)QUANT_ELEMS] = g_loss * 1.25f / (float)QUANT_ELEMS;
}

extern "C" void kernel_launch(void* const* d_in, const int* in_sizes, int n_in,
                              void* d_out, int out_size) {
    const float* Q = (const float*)d_in[0];   // [16,1024,256]
    const float* E = (const float*)d_in[1];   // [8192,256]
    float* out = (float*)d_out;

    rowsq_kernel<<<N_CODES / 8, 256>>>(E, N_CODES, 0);   // -> g_esq, zero g_loss
    rowsq_kernel<<<M_TOTAL / 8, 256>>>(Q, M_TOTAL, 1);   // -> g_qsq
    argmin_kernel<<<M_TOTAL / MT, 256>>>(Q, E);          // 128 CTAs
    gather_kernel<<<M_TOTAL, DIMC>>>(Q, E, out);         // 1 block / query
    final_kernel<<<1, 1>>>(out);
}

// round 6
// speedup vs baseline: 1.0162x; 1.0162x over previous
#include <cuda_runtime.h>

#define M_TOTAL 16384   // 16 * 1024 queries
#define N_CODES 8192
#define DIMC    256
#define QUANT_ELEMS (M_TOTAL * DIMC)

// ---- scratch (no device allocation allowed) ----
__device__ float g_esq[N_CODES];
__device__ float g_qsq[M_TOTAL];
__device__ unsigned long long g_best[M_TOTAL];  // (d_bits<<32)|idx, atomicMin-merged
__device__ float g_loss;

__device__ __forceinline__ unsigned f2tf32(float x) {
    unsigned r;
    asm("cvt.rna.tf32.f32 %0, %1;" : "=r"(r) : "f"(x));
    return r;
}

// ============================================================
// Kernel A: row squared-norms (one warp per 256-float row).
// which==0 -> g_esq (embedding), zeroes g_loss.
// which==1 -> g_qsq (queries), inits g_best to +inf keys.
// ============================================================
__global__ void rowsq_kernel(const float* __restrict__ src, int nrows, int which) {
    if (which == 0 && blockIdx.x == 0 && threadIdx.x == 0) g_loss = 0.0f;
    float* dst = which ? g_qsq : g_esq;
    int warp = (blockIdx.x * blockDim.x + threadIdx.x) >> 5;
    int lane = threadIdx.x & 31;
    if (warp >= nrows) return;
    const float4* row = (const float4*)(src + (size_t)warp * DIMC);
    float s = 0.0f;
    #pragma unroll
    for (int i = 0; i < 2; i++) {
        float4 v = row[lane + 32 * i];
        s += v.x * v.x + v.y * v.y + v.z * v.z + v.w * v.w;
    }
    #pragma unroll
    for (int o = 16; o > 0; o >>= 1) s += __shfl_xor_sync(0xFFFFFFFFu, s, o);
    if (lane == 0) {
        dst[warp] = s;
        if (which) g_best[warp] = 0xFFFFFFFFFFFFFFFFull;
    }
}

// ============================================================
// Exact rescore of one (query m, code n) pair. Sequential fmaf
// chain k=0..255 — identical rounding/order to the proven scalar
// kernel (matches jnp reference within ties). Merge via atomicMin
// on (d_bits<<32)|n: distances are ~256 (positive), so float-bit
// order == numeric order; equal d -> lowest n wins.
// ============================================================
__device__ __noinline__ void rescore(int m, int n,
                                     const float* __restrict__ Q,
                                     const float* __restrict__ E) {
    const float4* q4 = (const float4*)(Q + (size_t)m * DIMC);
    const float4* e4 = (const float4*)(E + (size_t)n * DIMC);
    float acc = 0.0f;
    #pragma unroll 8
    for (int i = 0; i < 64; i++) {
        float4 a = __ldg(q4 + i), b = __ldg(e4 + i);
        acc = fmaf(a.x, b.x, acc);
        acc = fmaf(a.y, b.y, acc);
        acc = fmaf(a.z, b.z, acc);
        acc = fmaf(a.w, b.w, acc);
    }
    float A = __fadd_rn(g_qsq[m], g_esq[n]);     // fl(q_sq + e_sq)
    float d = fmaf(-2.0f, acc, A);               // fl(A - 2*dot)
    unsigned long long key =
        ((unsigned long long)__float_as_uint(d) << 32) | (unsigned)n;
    atomicMin(&g_best[m], key);
}

// ============================================================
// Kernel B: TF32 tensor-core distance screen + exact rescore.
// CTA = 128 queries (8 warps x m16), sweeps all 8192 codes in
// NT=128 chunks, K staged in KC=32 slabs of smem (tf32-converted).
// Pass 0: per-row running min of s = e_sq - 2*dot_tf32.
// Pass 1: identical MMA math (bitwise-same s); codes with
//         s <= s_min + MARGIN rescored exactly.
// MARGIN = 0.02 (~140 sigma of the tf32 dot error) guarantees the
// exact argmin (and all its exact ties) are rescored.
// ============================================================
#define MT 128
#define NT 128
#define KC 32
#define KCP 36        // row pitch (floats): conflict-free frag loads
#define MARGIN 0.02f

__global__ __launch_bounds__(256)
void argmin_tc_kernel(const float* __restrict__ Q, const float* __restrict__ E) {
    __shared__ unsigned qs[MT * KCP];    // tf32 Q tile   (18 KB)
    __shared__ unsigned es[NT * KCP];    // tf32 E tile   (18 KB)
    __shared__ float    esq_s[NT];

    const int tid  = threadIdx.x;
    const int lane = tid & 31;
    const int warp = tid >> 5;
    const int qg   = lane & 3;           // quad index (k / col-pair select)
    const int gp   = lane >> 2;          // group (row / n select)
    const int m0   = blockIdx.x * MT;
    const int wrow = warp * 16;          // this warp's 16-row slice

    // running min of s over this thread's columns, rows wrow+gp / wrow+gp+8
    float smin0 = 3.4e38f, smin1 = 3.4e38f;
    float thr0 = 0.0f, thr1 = 0.0f;

    for (int pass = 0; pass < 2; pass++) {
        if (pass == 1) {
            // reduce across the 4 quad-threads covering each row
            #pragma unroll
            for (int o = 1; o <= 2; o <<= 1) {
                smin0 = fminf(smin0, __shfl_xor_sync(0xFFFFFFFFu, smin0, o));
                smin1 = fminf(smin1, __shfl_xor_sync(0xFFFFFFFFu, smin1, o));
            }
            thr0 = smin0 + MARGIN;
            thr1 = smin1 + MARGIN;
        }

        for (int n0 = 0; n0 < N_CODES; n0 += NT) {
            float c[16][4];
            #pragma unroll
            for (int j = 0; j < 16; j++)
                #pragma unroll
                for (int x = 0; x < 4; x++) c[j][x] = 0.0f;

            for (int k0 = 0; k0 < DIMC; k0 += KC) {
                // stage tf32 tiles (128 rows x 32 cols each)
                #pragma unroll
                for (int it = 0; it < 4; it++) {
                    int f4 = tid + 256 * it;     // 0..1023
                    int r  = f4 >> 3;
                    int c4 = f4 & 7;
                    float4 v = *(const float4*)(Q + (size_t)(m0 + r) * DIMC + k0 + c4 * 4);
                    qs[r * KCP + c4 * 4 + 0] = f2tf32(v.x);
                    qs[r * KCP + c4 * 4 + 1] = f2tf32(v.y);
                    qs[r * KCP + c4 * 4 + 2] = f2tf32(v.z);
                    qs[r * KCP + c4 * 4 + 3] = f2tf32(v.w);
                    float4 w = *(const float4*)(E + (size_t)(n0 + r) * DIMC + k0 + c4 * 4);
                    es[r * KCP + c4 * 4 + 0] = f2tf32(w.x);
                    es[r * KCP + c4 * 4 + 1] = f2tf32(w.y);
                    es[r * KCP + c4 * 4 + 2] = f2tf32(w.z);
                    es[r * KCP + c4 * 4 + 3] = f2tf32(w.w);
                }
                if (k0 == 0 && tid < NT) esq_s[tid] = g_esq[n0 + tid];
                __syncthreads();

                #pragma unroll
                for (int ks = 0; ks < KC; ks += 8) {
                    unsigned a0 = qs[(wrow + gp)     * KCP + ks + qg];
                    unsigned a1 = qs[(wrow + gp + 8) * KCP + ks + qg];
                    unsigned a2 = qs[(wrow + gp)     * KCP + ks + qg + 4];
                    unsigned a3 = qs[(wrow + gp + 8) * KCP + ks + qg + 4];
                    #pragma unroll
                    for (int j = 0; j < 16; j++) {
                        unsigned b0 = es[(j * 8 + gp) * KCP + ks + qg];
                        unsigned b1 = es[(j * 8 + gp) * KCP + ks + qg + 4];
                        asm("mma.sync.aligned.m16n8k8.row.col.f32.tf32.tf32.f32 "
                            "{%0,%1,%2,%3}, {%4,%5,%6,%7}, {%8,%9}, {%0,%1,%2,%3};"
                            : "+f"(c[j][0]), "+f"(c[j][1]), "+f"(c[j][2]), "+f"(c[j][3])
                            : "r"(a0), "r"(a1), "r"(a2), "r"(a3), "r"(b0), "r"(b1));
                    }
                }
                __syncthreads();
            }

            // epilogue: s = e_sq - 2*dot (q_sq constant per row -> irrelevant
            // to argmin; exact path re-adds it with reference rounding)
            if (pass == 0) {
                #pragma unroll
                for (int j = 0; j < 16; j++) {
                    float2 eq = *(const float2*)&esq_s[j * 8 + qg * 2];
                    float s0 = fmaf(-2.0f, c[j][0], eq.x);
                    float s1 = fmaf(-2.0f, c[j][1], eq.y);
                    float s2 = fmaf(-2.0f, c[j][2], eq.x);
                    float s3 = fmaf(-2.0f, c[j][3], eq.y);
                    smin0 = fminf(smin0, fminf(s0, s1));
                    smin1 = fminf(smin1, fminf(s2, s3));
                }
            } else {
                #pragma unroll
                for (int j = 0; j < 16; j++) {
                    float2 eq = *(const float2*)&esq_s[j * 8 + qg * 2];
                    float s0 = fmaf(-2.0f, c[j][0], eq.x);
                    float s1 = fmaf(-2.0f, c[j][1], eq.y);
                    float s2 = fmaf(-2.0f, c[j][2], eq.x);
                    float s3 = fmaf(-2.0f, c[j][3], eq.y);
                    int nb = n0 + j * 8 + qg * 2;
                    if (s0 <= thr0) rescore(m0 + wrow + gp,     nb,     Q, E);
                    if (s1 <= thr0) rescore(m0 + wrow + gp,     nb + 1, Q, E);
                    if (s2 <= thr1) rescore(m0 + wrow + gp + 8, nb,     Q, E);
                    if (s3 <= thr1) rescore(m0 + wrow + gp + 8, nb + 1, Q, E);
                }
            }
            __syncthreads();   // protect esq_s / tiles from next chunk's stores
        }
    }
}

// ============================================================
// Kernel C: gather quantized vectors, write indices + ST output,
// accumulate sum of (q - e)^2 for the loss. One block per query.
// ============================================================
__global__ void gather_kernel(const float* __restrict__ Q,
                              const float* __restrict__ E,
                              float* __restrict__ out) {
    const int m = blockIdx.x;
    const int c = threadIdx.x;           // 256 threads = DIMC
    const int idx = (int)(g_best[m] & 0xFFFFFFFFull);
    float q = Q[(size_t)m * DIMC + c];
    float e = E[(size_t)idx * DIMC + c];
    out[M_TOTAL + (size_t)m * DIMC + c] = __fadd_rn(q, __fsub_rn(e, q));
    float d = q - e;
    float s = d * d;
    #pragma unroll
    for (int o = 16; o > 0; o >>= 1) s += __shfl_xor_sync(0xFFFFFFFFu, s, o);
    __shared__ float ws[8];
    int lane = c & 31, warp = c >> 5;
    if (lane == 0) ws[warp] = s;
    __syncthreads();
    if (c == 0) {
        float t = 0.0f;
        #pragma unroll
        for (int w = 0; w < 8; w++) t += ws[w];
        atomicAdd(&g_loss, t);
        out[m] = (float)idx;
    }
}

// ============================================================
// Kernel D: finalize vq_loss = 1.25 * mean((q - e)^2)
// ============================================================
__global__ void final_kernel(float* __restrict__ out) {
    out[M_TOTAL + (size_t)QUANT_ELEMS] = g_loss * 1.25f / (float)QUANT_ELEMS;
}

extern "C" void kernel_launch(void* const* d_in, const int* in_sizes, int n_in,
                              void* d_out, int out_size) {
    const float* Q = (const float*)d_in[0];   // [16,1024,256]
    const float* E = (const float*)d_in[1];   // [8192,256]
    float* out = (float*)d_out;

    rowsq_kernel<<<N_CODES / 8, 256>>>(E, N_CODES, 0);   // g_esq, zero loss
    rowsq_kernel<<<M_TOTAL / 8, 256>>>(Q, M_TOTAL, 1);   // g_qsq, init g_best
    argmin_tc_kernel<<<M_TOTAL / MT, 256>>>(Q, E);       // 128 CTAs
    gather_kernel<<<M_TOTAL, DIMC>>>(Q, E, out);
    final_kernel<<<1, 1>>>(out);
}

// round 9
// speedup vs baseline: 2.5139x; 2.4739x over previous
#include <cuda_runtime.h>
#include <cstdint>

#define M_TOTAL 16384
#define N_CODES 8192
#define DIMC    256
#define QUANT_ELEMS (M_TOTAL * DIMC)

#define MT 128
#define NT 128
#define NTILES (N_CODES / NT)         // 64
#define NSLABS (NTILES * 4)           // 256 (each slab = 64 k-values)
#define MARGIN 0.08f

// SMEM (uint32 pitches chosen ≡ 8 mod 32 -> conflict-free LDS.64 frag reads)
#define QPITCH 136                    // 128 bf16x2 + pad
#define EPITCH 40                     // 32 bf16x2 + pad
#define SM_ESQ  0                     // 2 * 128 floats = 1024 B
#define SM_Q    1024                  // 128*136*4 = 69632 B
#define SM_E    (1024 + 69632)        // 2 * 128*40*4 = 40960 B
#define SM_TOTAL (1024 + 69632 + 40960)   // 111616 B

// k-pair permutation: pair P stored at ((P>>3)<<3) | (((P&3)<<1)|((P>>2)&1))
// so a thread's pairs (qg, qg+4) of each 8-group sit adjacent -> one LDS.64.
#define DST(P) ((((P) >> 3) << 3) | ((((P) & 3) << 1) | (((P) >> 2) & 1)))

__device__ float g_esq[N_CODES];
__device__ float g_qsq[M_TOTAL];
__device__ unsigned long long g_best[M_TOTAL];   // (d_bits<<32)|idx
__device__ float g_loss;

__device__ __forceinline__ uint32_t pack_bf16x2(float lo, float hi) {
    uint32_t r;
    asm("cvt.rn.bf16x2.f32 %0, %1, %2;" : "=r"(r) : "f"(hi), "f"(lo));
    return r;
}
__device__ __forceinline__ void mma_bf16(float c[4],
                                         uint32_t a0, uint32_t a1, uint32_t a2, uint32_t a3,
                                         uint32_t b0, uint32_t b1) {
    asm("mma.sync.aligned.m16n8k16.row.col.f32.bf16.bf16.f32 "
        "{%0,%1,%2,%3}, {%4,%5,%6,%7}, {%8,%9}, {%0,%1,%2,%3};"
        : "+f"(c[0]), "+f"(c[1]), "+f"(c[2]), "+f"(c[3])
        : "r"(a0), "r"(a1), "r"(a2), "r"(a3), "r"(b0), "r"(b1));
}

// ============================================================
// Kernel A: row squared-norms (warp/row). which==0 -> g_esq (+zero loss),
// which==1 -> g_qsq (+init g_best).
// ============================================================
__global__ void rowsq_kernel(const float* __restrict__ src, int nrows, int which) {
    if (which == 0 && blockIdx.x == 0 && threadIdx.x == 0) g_loss = 0.0f;
    float* dst = which ? g_qsq : g_esq;
    int warp = (blockIdx.x * blockDim.x + threadIdx.x) >> 5;
    int lane = threadIdx.x & 31;
    if (warp >= nrows) return;
    const float4* row = (const float4*)(src + (size_t)warp * DIMC);
    float s = 0.0f;
    #pragma unroll
    for (int i = 0; i < 2; i++) {
        float4 v = row[lane + 32 * i];
        s += v.x * v.x + v.y * v.y + v.z * v.z + v.w * v.w;
    }
    #pragma unroll
    for (int o = 16; o > 0; o >>= 1) s += __shfl_xor_sync(0xFFFFFFFFu, s, o);
    if (lane == 0) {
        dst[warp] = s;
        if (which) g_best[warp] = 0xFFFFFFFFFFFFFFFFull;
    }
}

// Exact rescore (proven R4/R6 rounding chain): sequential fmaf k=0..255,
// A = fl(q_sq+e_sq), d = fl(A - 2*dot). atomicMin on (d_bits<<32)|n:
// d>0 -> float-bit order == numeric order; equal d -> lowest n wins.
__device__ __noinline__ void rescore(int m, int n,
                                     const float* __restrict__ Q,
                                     const float* __restrict__ E) {
    const float4* q4 = (const float4*)(Q + (size_t)m * DIMC);
    const float4* e4 = (const float4*)(E + (size_t)n * DIMC);
    float acc = 0.0f;
    #pragma unroll 8
    for (int i = 0; i < 64; i++) {
        float4 a = __ldg(q4 + i), b = __ldg(e4 + i);
        acc = fmaf(a.x, b.x, acc);
        acc = fmaf(a.y, b.y, acc);
        acc = fmaf(a.z, b.z, acc);
        acc = fmaf(a.w, b.w, acc);
    }
    float A = __fadd_rn(g_qsq[m], g_esq[n]);
    float d = fmaf(-2.0f, acc, A);
    unsigned long long key =
        ((unsigned long long)__float_as_uint(d) << 32) | (unsigned)n;
    atomicMin(&g_best[m], key);
}

// ============================================================
// Kernel B: bf16 HMMA screen + online exact rescore. Single pass.
// CTA = 128 queries; 8 warps x 16 rows. 64 tiles of 128 codes,
// each tile = 4 double-buffered E slabs (128 rows x 64 k bf16).
// Q resident in SMEM as bf16 (converted once).
// ============================================================
__global__ __launch_bounds__(256, 1)
void argmin_bf16(const float* __restrict__ Q, const float* __restrict__ E) {
    extern __shared__ char smem[];
    float*    esq_s = (float*)(smem + SM_ESQ);
    uint32_t* qsm   = (uint32_t*)(smem + SM_Q);
    uint32_t* esm   = (uint32_t*)(smem + SM_E);

    const int tid  = threadIdx.x;
    const int lane = tid & 31;
    const int qg   = lane & 3;
    const int gp   = lane >> 2;
    const int wrow = (tid >> 5) * 16;
    const int m0   = blockIdx.x * MT;
    const int m_lo = m0 + wrow + gp;
    const int m_hi = m_lo + 8;

    // ---- stage Q (128 x 256 fp32 -> bf16x2, permuted) ----
    #pragma unroll 4
    for (int i = 0; i < 32; i++) {
        int idx = tid + 256 * i;
        int r = idx >> 6, c4 = idx & 63;
        float4 v = __ldg((const float4*)(Q + (size_t)(m0 + r) * DIMC) + c4);
        int P0 = c4 * 2;
        qsm[r * QPITCH + DST(P0)]     = pack_bf16x2(v.x, v.y);
        qsm[r * QPITCH + DST(P0 + 1)] = pack_bf16x2(v.z, v.w);
    }

    float c[16][4];
    float smin_lo = 3.4e38f, smin_hi = 3.4e38f;

    // prefetch slab 0
    float4 pf[8];
    {
        const float4* base = (const float4*)(E);
        #pragma unroll
        for (int u = 0; u < 8; u++) {
            int j = tid + 256 * u;
            int r = j >> 4, c4 = j & 15;
            pf[u] = __ldg((const float4*)(E + (size_t)r * DIMC) + c4);
        }
        (void)base;
    }

    for (int idx = 0; idx < NSLABS; idx++) {
        const int t = idx >> 2, s = idx & 3, buf = idx & 1;
        uint32_t* eb = esm + buf * (128 * EPITCH);

        __syncthreads();   // prior compute on this buffer done; qsm ready (idx 0)

        // store prefetched slab (convert to bf16x2, permuted)
        #pragma unroll
        for (int u = 0; u < 8; u++) {
            int j = tid + 256 * u;
            int r = j >> 4, c4 = j & 15;
            int P0 = c4 * 2;
            eb[r * EPITCH + DST(P0)]     = pack_bf16x2(pf[u].x, pf[u].y);
            eb[r * EPITCH + DST(P0 + 1)] = pack_bf16x2(pf[u].z, pf[u].w);
        }
        if (s == 0 && tid < 128)
            esq_s[(t & 1) * 128 + tid] = __ldg(&g_esq[t * NT + tid]);

        // prefetch next slab
        if (idx + 1 < NSLABS) {
            int t2 = (idx + 1) >> 2, s2 = (idx + 1) & 3;
            const float* eb2 = E + (size_t)t2 * NT * DIMC + s2 * 64;
            #pragma unroll
            for (int u = 0; u < 8; u++) {
                int j = tid + 256 * u;
                int r = j >> 4, c4 = j & 15;
                pf[u] = __ldg((const float4*)(eb2 + (size_t)r * DIMC) + c4);
            }
        }

        __syncthreads();   // slab visible

        if (s == 0) {
            #pragma unroll
            for (int j = 0; j < 16; j++)
                #pragma unroll
                for (int x = 0; x < 4; x++) c[j][x] = 0.0f;
        }

        // 4 k16-steps over this slab
        #pragma unroll
        for (int tt = 0; tt < 4; tt++) {
            int kt = s * 4 + tt;
            uint2 A0 = *(const uint2*)&qsm[(wrow + gp)     * QPITCH + kt * 8 + qg * 2];
            uint2 A1 = *(const uint2*)&qsm[(wrow + gp + 8) * QPITCH + kt * 8 + qg * 2];
            #pragma unroll
            for (int j = 0; j < 16; j++) {
                uint2 B = *(const uint2*)&eb[(j * 8 + gp) * EPITCH + tt * 8 + qg * 2];
                mma_bf16(c[j], A0.x, A1.x, A0.y, A1.y, B.x, B.y);
            }
        }

        if (s == 3) {
            // epilogue: s = e_sq - 2*dot (in place), tile min, online rescore
            const float* eq = esq_s + (t & 1) * 128;
            float tlo = 3.4e38f, thi = 3.4e38f;
            #pragma unroll
            for (int j = 0; j < 16; j++) {
                float e0 = eq[j * 8 + qg * 2];
                float e1 = eq[j * 8 + qg * 2 + 1];
                c[j][0] = fmaf(-2.0f, c[j][0], e0);
                c[j][1] = fmaf(-2.0f, c[j][1], e1);
                c[j][2] = fmaf(-2.0f, c[j][2], e0);
                c[j][3] = fmaf(-2.0f, c[j][3], e1);
                tlo = fminf(tlo, fminf(c[j][0], c[j][1]));
                thi = fminf(thi, fminf(c[j][2], c[j][3]));
            }
            // per-row tile min across the 4 quad threads (lane bits 0,1)
            tlo = fminf(tlo, __shfl_xor_sync(0xFFFFFFFFu, tlo, 1));
            tlo = fminf(tlo, __shfl_xor_sync(0xFFFFFFFFu, tlo, 2));
            thi = fminf(thi, __shfl_xor_sync(0xFFFFFFFFu, thi, 1));
            thi = fminf(thi, __shfl_xor_sync(0xFFFFFFFFu, thi, 2));
            float thrlo = fminf(smin_lo, tlo) + MARGIN;
            float thrhi = fminf(smin_hi, thi) + MARGIN;
            #pragma unroll
            for (int j = 0; j < 16; j++) {
                int nb = t * NT + j * 8 + qg * 2;
                if (c[j][0] <= thrlo) rescore(m_lo, nb,     Q, E);
                if (c[j][1] <= thrlo) rescore(m_lo, nb + 1, Q, E);
                if (c[j][2] <= thrhi) rescore(m_hi, nb,     Q, E);
                if (c[j][3] <= thrhi) rescore(m_hi, nb + 1, Q, E);
            }
            smin_lo = fminf(smin_lo, tlo);
            smin_hi = fminf(smin_hi, thi);
        }
    }
}

// ============================================================
// Kernel C: gather + ST output + loss partials.
// ============================================================
__global__ void gather_kernel(const float* __restrict__ Q,
                              const float* __restrict__ E,
                              float* __restrict__ out) {
    const int m = blockIdx.x;
    const int c = threadIdx.x;
    const int idx = (int)(g_best[m] & 0xFFFFFFFFull);
    float q = Q[(size_t)m * DIMC + c];
    float e = E[(size_t)idx * DIMC + c];
    out[M_TOTAL + (size_t)m * DIMC + c] = __fadd_rn(q, __fsub_rn(e, q));
    float d = q - e;
    float s = d * d;
    #pragma unroll
    for (int o = 16; o > 0; o >>= 1) s += __shfl_xor_sync(0xFFFFFFFFu, s, o);
    __shared__ float ws[8];
    int lane = c & 31, warp = c >> 5;
    if (lane == 0) ws[warp] = s;
    __syncthreads();
    if (c == 0) {
        float t = 0.0f;
        #pragma unroll
        for (int w = 0; w < 8; w++) t += ws[w];
        atomicAdd(&g_loss, t);
        out[m] = (float)idx;
    }
}

__global__ void final_kernel(float* __restrict__ out) {
    out[M_TOTAL + (size_t)QUANT_ELEMS] = g_loss * 1.25f / (float)QUANT_ELEMS;
}

extern "C" void kernel_launch(void* const* d_in, const int* in_sizes, int n_in,
                              void* d_out, int out_size) {
    const float* Q = (const float*)d_in[0];   // [16,1024,256]
    const float* E = (const float*)d_in[1];   // [8192,256]
    float* out = (float*)d_out;

    static int smem_set = 0;
    if (!smem_set) {
        cudaFuncSetAttribute(argmin_bf16,
                             cudaFuncAttributeMaxDynamicSharedMemorySize, SM_TOTAL);
        smem_set = 1;
    }

    rowsq_kernel<<<N_CODES / 8, 256>>>(E, N_CODES, 0);   // g_esq, zero loss
    rowsq_kernel<<<M_TOTAL / 8, 256>>>(Q, M_TOTAL, 1);   // g_qsq, init g_best
    argmin_bf16<<<M_TOTAL / MT, 256, SM_TOTAL>>>(Q, E);
    gather_kernel<<<M_TOTAL, DIMC>>>(Q, E, out);
    final_kernel<<<1, 1>>>(out);
}